// round 2
// baseline (speedup 1.0000x reference)
#include <cuda_runtime.h>
#include <cstdint>

#define EPS   1e-9f
#define ITERS 20
#define LDK   68      // padded shared row stride in floats (17 float4)

typedef unsigned long long ull;

__device__ __forceinline__ ull pack2f(float lo, float hi) {
    ull r; asm("mov.b64 %0, {%1, %2};" : "=l"(r) : "f"(lo), "f"(hi)); return r;
}
__device__ __forceinline__ void unpack2f(ull p, float& lo, float& hi) {
    asm("mov.b64 {%0, %1}, %2;" : "=f"(lo), "=f"(hi) : "l"(p));
}
// packed 2xfp32 FMA — only reachable via PTX fma.rn.f32x2 (sm_10x)
__device__ __forceinline__ ull ffma2(ull a, ull b, ull c) {
    ull d; asm("fma.rn.f32x2 %0, %1, %2, %3;" : "=l"(d) : "l"(a), "l"(b), "l"(c)); return d;
}

__global__ __launch_bounds__(64)
void sinkhorn_kernel(const float* __restrict__ x, float* __restrict__ out)
{
    __shared__ __align__(16) float shK[64 * LDK];
    __shared__ __align__(16) float shv[64];
    __shared__ __align__(16) float shu[64];

    const int tid = threadIdx.x;
    const long long m = blockIdx.x;
    const float4* __restrict__ x4 = reinterpret_cast<const float4*>(x) + m * 1024;
    float4* __restrict__ o4       = reinterpret_cast<float4*>(out)     + m * 1024;

    // ---- coalesced load, exp, stage into padded shared -------------------
    #pragma unroll
    for (int j = 0; j < 16; j++) {
        int e4 = j * 64 + tid;            // float4 linear index within matrix
        float4 t = x4[e4];
        int row = e4 >> 4;
        int c4  = e4 & 15;
        float4 e;
        e.x = __expf(t.x); e.y = __expf(t.y);
        e.z = __expf(t.z); e.w = __expf(t.w);
        reinterpret_cast<float4*>(shK)[row * 17 + c4] = e;
    }
    shv[tid] = 1.0f;
    __syncthreads();

    // ---- gather row tid and column tid of K into packed registers --------
    ull kr[32];   // K[tid][0..63] as 32 float2
    ull kc[32];   // K[0..63][tid] as 32 float2 (pairs of rows)
    #pragma unroll
    for (int j = 0; j < 16; j++) {
        float4 t = reinterpret_cast<const float4*>(shK)[tid * 17 + j];
        kr[2 * j]     = pack2f(t.x, t.y);
        kr[2 * j + 1] = pack2f(t.z, t.w);
    }
    #pragma unroll
    for (int j = 0; j < 32; j++) {
        kc[j] = pack2f(shK[(2 * j) * LDK + tid], shK[(2 * j + 1) * LDK + tid]);
    }

    float u = 1.0f, v = 1.0f;

    #pragma unroll 1
    for (int it = 0; it < ITERS; it++) {
        // row matvec: dot = K[tid,:] . v     (v broadcast from shared)
        ull acc = 0ull;
        #pragma unroll
        for (int j = 0; j < 16; j++) {
            float4 vv = reinterpret_cast<const float4*>(shv)[j];
            acc = ffma2(kr[2 * j],     pack2f(vv.x, vv.y), acc);
            acc = ffma2(kr[2 * j + 1], pack2f(vv.z, vv.w), acc);
        }
        float d0, d1; unpack2f(acc, d0, d1);
        float dot = d0 + d1;
        u = __fdividef(u, fmaf(u, dot, EPS));
        shu[tid] = u;
        __syncthreads();

        // col matvec: cs = K[:,tid] . u'    (u broadcast from shared)
        ull acc2 = 0ull;
        #pragma unroll
        for (int j = 0; j < 16; j++) {
            float4 uu = reinterpret_cast<const float4*>(shu)[j];
            acc2 = ffma2(kc[2 * j],     pack2f(uu.x, uu.y), acc2);
            acc2 = ffma2(kc[2 * j + 1], pack2f(uu.z, uu.w), acc2);
        }
        float c0, c1; unpack2f(acc2, c0, c1);
        float cs = c0 + c1;
        v = __fdividef(v, fmaf(v, cs, EPS));
        shv[tid] = v;
        __syncthreads();
    }

    // ---- output M = diag(u) K diag(v), staged through shared for coalescing
    #pragma unroll
    for (int j = 0; j < 16; j++) {
        float4 vv = reinterpret_cast<const float4*>(shv)[j];
        float k0, k1, k2, k3;
        unpack2f(kr[2 * j],     k0, k1);
        unpack2f(kr[2 * j + 1], k2, k3);
        float4 r;
        r.x = u * k0 * vv.x; r.y = u * k1 * vv.y;
        r.z = u * k2 * vv.z; r.w = u * k3 * vv.w;
        reinterpret_cast<float4*>(shK)[tid * 17 + j] = r;
    }
    __syncthreads();
    #pragma unroll
    for (int j = 0; j < 16; j++) {
        int e4 = j * 64 + tid;
        int row = e4 >> 4;
        int c4  = e4 & 15;
        o4[e4] = reinterpret_cast<const float4*>(shK)[row * 17 + c4];
    }
}

extern "C" void kernel_launch(void* const* d_in, const int* in_sizes, int n_in,
                              void* d_out, int out_size)
{
    const float* x = (const float*)d_in[0];
    float* out = (float*)d_out;
    int nmat = in_sizes[0] / 4096;   // 64*64 elements per matrix
    sinkhorn_kernel<<<nmat, 64>>>(x, out);
}